// round 14
// baseline (speedup 1.0000x reference)
#include <cuda_runtime.h>
#include <cuda_bf16.h>
#include <cuda_fp16.h>
#include <math_constants.h>

#define FULL 0xffffffffu

static constexpr int B = 8;
static constexpr int N = 4096;
static constexpr int C = 128;
static constexpr int KNN = 16;

typedef unsigned long long ull;

// scratch (device globals: no allocation allowed)
__device__ __half g_zbn[B * N * C];    // zbn[b][n][c] fp16, n-major rows 256B
__device__ float4 g_srt[B * N];        // points in Morton-rank order (x,y,z,|p|^2)
__device__ int    g_sidx[B * N];       // Morton rank -> original index
__device__ int    g_idx[B * N * KNN];  // 16 NN orig indices per query

// ---------------------------------------------------------------------------
// dummy kernel (launch-slot shim so ncu's flat launch #3 is the fused kernel)
// ---------------------------------------------------------------------------
__global__ void dummy_kernel() {}

// ---------------------------------------------------------------------------
// Kernel 0: per-batch Morton counting sort (prep absorbed: loads xyz, computes
// norms inline, scatters points + orig indices in Morton-rank order).
// One 512-thread block per batch. Order within a cell is nondeterministic but
// per-query KNN output is order-independent -> deterministic results.
// ---------------------------------------------------------------------------
__device__ __forceinline__ int part4(int v) {
    return (v & 1) | ((v & 2) << 2) | ((v & 4) << 4) | ((v & 8) << 6);
}

__global__ __launch_bounds__(512) void qsort_kernel(const float* __restrict__ xyz)
{
    __shared__ int hist[4096];
    __shared__ int tsum[512];

    const int b   = blockIdx.x;
    const int tid = threadIdx.x;

    for (int i = tid; i < 4096; i += 512) hist[i] = 0;
    __syncthreads();

    float4 p[8];
    int cell[8];
#pragma unroll
    for (int k = 0; k < 8; ++k) {
        int i = tid + k * 512;
        const float* src = xyz + ((size_t)b * N + i) * 3;
        float px = src[0], py = src[1], pz = src[2];
        p[k] = make_float4(px, py, pz, px * px + py * py + pz * pz);
        int ix = min(15, max(0, (int)(px * 2.5f + 8.0f)));
        int iy = min(15, max(0, (int)(py * 2.5f + 8.0f)));
        int iz = min(15, max(0, (int)(pz * 2.5f + 8.0f)));
        int m = (part4(ix) << 2) | (part4(iy) << 1) | part4(iz);
        cell[k] = m;
        atomicAdd(&hist[m], 1);
    }
    __syncthreads();

    // exclusive prefix sum over 4096 bins (8 per thread + Hillis-Steele)
    const int base = tid * 8;
    int s = 0;
#pragma unroll
    for (int j = 0; j < 8; ++j) s += hist[base + j];
    tsum[tid] = s;
    __syncthreads();
    for (int off = 1; off < 512; off <<= 1) {
        int v = (tid >= off) ? tsum[tid - off] : 0;
        __syncthreads();
        tsum[tid] += v;
        __syncthreads();
    }
    int run = (tid ? tsum[tid - 1] : 0);
#pragma unroll
    for (int j = 0; j < 8; ++j) { int h = hist[base + j]; hist[base + j] = run; run += h; }
    __syncthreads();

    // scatter: rank = atomic cursor within cell
#pragma unroll
    for (int k = 0; k < 8; ++k) {
        int i = tid + k * 512;
        int r = atomicAdd(&hist[cell[k]], 1);
        g_srt[(size_t)b * N + r]  = p[k];
        g_sidx[(size_t)b * N + r] = i;
    }
}

// ---------------------------------------------------------------------------
// Role A: GEMM + BN + ReLU -> fp16 zbn. 64n x 64c tile, 16 acc/thread.
// ---------------------------------------------------------------------------
__device__ __forceinline__ void gemm_role(
    char* smem_raw, int gb,
    const float* __restrict__ x, const float* __restrict__ W,
    const float* __restrict__ gamma, const float* __restrict__ beta,
    const float* __restrict__ rmean, const float* __restrict__ rvar)
{
    float (*xs)[64] = (float(*)[64])smem_raw;                  // [32][64]
    float (*ws)[64] = (float(*)[64])(smem_raw + 32 * 64 * 4);  // [32][64] swizzled

    const int b      = gb >> 7;          // /128
    const int rem    = gb & 127;
    const int chalf  = rem >> 6;         // c-half 0/1
    const int n0     = (rem & 63) * 64;
    const int c0base = chalf * 64;

    const int tid = threadIdx.x;
    const int tc  = tid & 15;            // 16 c-groups x 4c
    const int tn  = tid >> 4;            // 16 n-groups x 4n

    float acc[4][4];
#pragma unroll
    for (int j = 0; j < 4; ++j)
#pragma unroll
        for (int i = 0; i < 4; ++i) acc[j][i] = 0.0f;

    const float* xb = x + (size_t)b * C * N;

    for (int k0 = 0; k0 < C; k0 += 32) {
#pragma unroll
        for (int i = tid; i < 32 * 64; i += 256) {
            int kk = i >> 6, nn = i & 63;
            xs[kk][nn] = xb[(size_t)(k0 + kk) * N + n0 + nn];
        }
#pragma unroll
        for (int i = tid; i < 32 * 64; i += 256) {
            int c = i >> 5, kk = i & 31;   // c' 0..63
            ws[kk][c ^ ((kk & 15) << 2)] = W[(c0base + c) * C + k0 + kk];
        }
        __syncthreads();

#pragma unroll
        for (int kk = 0; kk < 32; ++kk) {
            float4 wv = *(const float4*)&ws[kk][((tc ^ (kk & 15)) << 2)];
            float4 xv = *(const float4*)&xs[kk][tn * 4];
            float wj[4] = {wv.x, wv.y, wv.z, wv.w};
            float xi[4] = {xv.x, xv.y, xv.z, xv.w};
#pragma unroll
            for (int j = 0; j < 4; ++j)
#pragma unroll
                for (int i = 0; i < 4; ++i)
                    acc[j][i] = fmaf(wj[j], xi[i], acc[j][i]);
        }
        __syncthreads();
    }

    const int c0 = c0base + tc * 4;
    float sc[4], bi[4];
#pragma unroll
    for (int j = 0; j < 4; ++j) {
        sc[j] = gamma[c0 + j] * rsqrtf(rvar[c0 + j] + 1e-5f);
        bi[j] = beta[c0 + j] - rmean[c0 + j] * sc[j];
    }
#pragma unroll
    for (int i = 0; i < 4; ++i) {
        int n = n0 + tn * 4 + i;
        float ox = fmaxf(fmaf(acc[0][i], sc[0], bi[0]), 0.0f);
        float oy = fmaxf(fmaf(acc[1][i], sc[1], bi[1]), 0.0f);
        float oz = fmaxf(fmaf(acc[2][i], sc[2], bi[2]), 0.0f);
        float ow = fmaxf(fmaf(acc[3][i], sc[3], bi[3]), 0.0f);
        __half2 h01 = __floats2half2_rn(ox, oy);
        __half2 h23 = __floats2half2_rn(oz, ow);
        uint2 u;
        u.x = *reinterpret_cast<unsigned*>(&h01);
        u.y = *reinterpret_cast<unsigned*>(&h23);
        *(uint2*)&g_zbn[((size_t)b * N + n) * C + c0] = u;
    }
}

// ---------------------------------------------------------------------------
// Role B: top-16 KNN over Morton-rank candidate space. Queries = consecutive
// ranks (warp lanes spatially adjacent); candidate chunks iterated with a
// per-block rotation so iteration 0 stages the block's own spatial
// neighborhood -> threshold converges immediately -> few accepts.
// Splits scan disjoint rank ranges; all 4096 ranks covered exactly once.
// ---------------------------------------------------------------------------
__device__ __forceinline__ void insert16(float (&tv)[16], int (&ti)[16],
                                         float e, int jj)
{
#pragma unroll
    for (int t = 15; t >= 0; --t) {
        bool gt  = tv[t] > e;                   // strict: ties keep incumbent
        bool gtp = (t > 0) && (tv[t - 1] > e);
        float nv = gtp ? tv[t - 1] : e;
        int   ni = gtp ? ti[t - 1] : jj;
        if (gt) { tv[t] = nv; ti[t] = ni; }
    }
}

__device__ __forceinline__ void knn_role(char* smem_raw, int kb)
{
    ull    (*buf)[256] = (ull(*)[256])smem_raw;                  // [16][256] 32KB
    float4* tile = (float4*)(smem_raw + 16 * 256 * 8);           // [1024] 16KB
    float  (*sthr)[5] = (float(*)[5])(smem_raw + 16 * 256 * 8 + 1024 * 16);

    const int tid  = threadIdx.x;
    const int u    = tid & 63;                   // query slot in block
    const int s    = tid >> 6;                   // split 0..3 (warp-homogeneous)
    const int b    = kb >> 6;                    // batch
    const int w    = kb & 63;                    // query-window id
    const int qrk  = w * 64 + u;                 // my query's Morton rank
    const int c0   = (w >> 2) & 3;               // chunk rotation: home chunk first

    // init shared thresholds
    for (int i = tid; i < 64 * 5; i += 256) ((float*)sthr)[i] = CUDART_INF_F;

    const float4* __restrict__ xb = g_srt + (size_t)b * N;
    const float4 Q = __ldg(&xb[qrk]);
    const float qs = Q.w;

    float tv[16]; int ti[16];
#pragma unroll
    for (int t = 0; t < 16; ++t) { tv[t] = CUDART_INF_F; ti[t] = 0; }

    const int lo = s << 10;                      // s * 1024
    const float4* __restrict__ mychunk = tile + (s << 8);

    unsigned addr0 = (unsigned)__cvta_generic_to_shared(&buf[0][0]) + tid * 8u;
    unsigned addr  = addr0;
    const unsigned athr = addr0 + 8u * 2048u;    // trigger: cnt >= 8 (stride 2048)
    float fthr = CUDART_INF_F;

#define KNN_FLUSH() do {                                                      \
        int cnt = (int)((addr - addr0) >> 11);                                \
        int mx  = __reduce_max_sync(FULL, cnt);                               \
        for (int t = 0; t < mx; ++t) {                                        \
            ull e = buf[t][tid];                                              \
            float ed = (t < cnt) ? __uint_as_float((unsigned)(e >> 32))       \
                                 : CUDART_INF_F;                              \
            int   ej = (int)(unsigned)e;                                      \
            insert16(tv, ti, ed, ej);                                         \
        }                                                                     \
        addr = addr0;                                                         \
        sthr[u][s] = tv[15];                                                  \
        fthr = fminf(fminf(sthr[u][0], sthr[u][1]),                           \
                     fminf(sthr[u][2], sthr[u][3]));                          \
    } while (0)

#pragma unroll 1
    for (int it = 0; it < 4; ++it) {
        const int cc = (it + c0) & 3;            // rotated chunk index

        // ---- stage 4x256 chunk tile (coalesced; barrier protects reads) ----
        __syncthreads();
#pragma unroll
        for (int k = 0; k < 4; ++k) {
            int flat = tid + (k << 8);           // 0..1023
            int ch = flat >> 8, off = flat & 255;
            tile[flat] = __ldg(&xb[(ch << 10) + (cc << 8) + off]);
        }
        __syncthreads();

        const int jbase = lo + (cc << 8);        // rank base of my chunk
        int t0 = 0;

        if (it == 0) {
            // ---- seed: first 16 candidates of home-rotated chunk ----
#pragma unroll 1
            for (int jj = 0; jj < 16; ++jj) {
                float4 p = mychunk[jj];
                float dot = Q.x * p.x;
                dot = fmaf(Q.y, p.y, dot);
                dot = fmaf(Q.z, p.z, dot);
                float d = fmaf(-2.0f, dot, qs + p.w);
                insert16(tv, ti, d, jbase + jj);
            }
            sthr[u][s] = tv[15];
            fthr = fminf(fminf(sthr[u][0], sthr[u][1]),
                         fminf(sthr[u][2], sthr[u][3]));
            t0 = 16;
        }

        // ---- scan chunk: two 4-candidate phases (A: distances, B: accepts),
        //      flush check per 8 candidates ----
#pragma unroll 1
        for (; t0 < 256; t0 += 8) {
#pragma unroll
            for (int h = 0; h < 2; ++h) {
                float d[4];
#pragma unroll
                for (int uu = 0; uu < 4; ++uu) {
                    float4 p = mychunk[t0 + 4 * h + uu];
                    float dot = Q.x * p.x;
                    dot = fmaf(Q.y, p.y, dot);
                    dot = fmaf(Q.z, p.z, dot);
                    d[uu] = fmaf(-2.0f, dot, qs + p.w);
                }
#pragma unroll
                for (int uu = 0; uu < 4; ++uu) {
                    int j = jbase + t0 + 4 * h + uu;
                    unsigned db = __float_as_uint(d[uu]);
                    asm volatile(
                        "{\n\t"
                        ".reg .pred p;\n\t"
                        "setp.lt.f32 p, %1, %2;\n\t"
                        "@p st.shared.v2.b32 [%0], {%3, %4};\n\t"
                        "@p add.u32 %0, %0, 2048;\n\t"
                        "}"
                        : "+r"(addr) : "f"(d[uu]), "f"(fthr), "r"(j), "r"(db) : "memory");
                }
            }
            if (__any_sync(FULL, addr >= athr)) KNN_FLUSH();
        }
    }
    // ---- final flush ----
    if (__any_sync(FULL, addr != addr0)) KNN_FLUSH();
#undef KNN_FLUSH

    // ---- merge splits 1..3 into split 0; splits scan disjoint rank ranges
    //      so no dedup needed. Staging overlays the dead accept buffer. ----
    __syncthreads();                             // all flush reads of buf done
    float (*mD)[3][17] = (float(*)[3][17])&buf[0][0];
    int   (*mI)[3][17] = (int(*)[3][17])((float*)&buf[0][0] + 64 * 3 * 17);

    if (s != 0) {
#pragma unroll
        for (int t = 0; t < 16; ++t) {
            mD[u][s - 1][t] = tv[t];
            mI[u][s - 1][t] = ti[t];
        }
    }
    __syncthreads();
    if (s == 0) {
#pragma unroll 1
        for (int k = 0; k < 3; ++k)
#pragma unroll 1
            for (int t = 0; t < 16; ++t)
                insert16(tv, ti, mD[u][k][t], mI[u][k][t]);

        // map ranks -> original indices; write to the query's original slot
        const int* __restrict__ sidx = g_sidx + (size_t)b * N;
        int orig = __ldg(&sidx[qrk]);
        int* op = g_idx + ((size_t)b * N + orig) * KNN;
#pragma unroll
        for (int t = 0; t < 16; ++t) op[t] = __ldg(&sidx[ti[t]]);
    }
}

// ---------------------------------------------------------------------------
// Fused kernel: blocks [0,512) = KNN (long pole, scheduled first);
// blocks [512,1536) = GEMM (backfills, FFMA fills KNN's ALU-stall slots).
// __launch_bounds__(256,4): 64-reg ceiling -> 4 blocks/SM with 50KB smem.
// ---------------------------------------------------------------------------
extern __shared__ char smem_raw[];

__global__ __launch_bounds__(256, 4) void fused_kernel(
    const float* __restrict__ x, const float* __restrict__ W,
    const float* __restrict__ gamma, const float* __restrict__ beta,
    const float* __restrict__ rmean, const float* __restrict__ rvar)
{
    int bx = blockIdx.x;
    if (bx < 512)
        knn_role(smem_raw, bx);
    else
        gemm_role(smem_raw, bx - 512, x, W, gamma, beta, rmean, rvar);
}

// ---------------------------------------------------------------------------
// Kernel 3: gather-max over 16 neighbors (fp16 rows) + transpose to [B][C][N].
// ---------------------------------------------------------------------------
__global__ __launch_bounds__(256) void gather_kernel(float* __restrict__ out)
{
    __shared__ float sout[128][33];

    const int b    = blockIdx.y;
    const int n0   = blockIdx.x * 32;
    const int tid  = threadIdx.x;
    const int w    = tid >> 5;
    const int lane = tid & 31;

    const __half* __restrict__ zb = g_zbn + (size_t)b * N * C;

    for (int s = 0; s < 4; ++s) {
        const int ql = w * 4 + s;
        const int n  = n0 + ql;
        int myidx = (lane < 16) ? g_idx[((size_t)b * N + n) * KNN + lane] : 0;

        __half2 m01 = __float2half2_rn(0.0f);   // post-ReLU >= 0
        __half2 m23 = __float2half2_rn(0.0f);
#pragma unroll
        for (int t = 0; t < KNN; t += 2) {
            int j1 = __shfl_sync(FULL, myidx, t);
            int j2 = __shfl_sync(FULL, myidx, t + 1);
            const uint2* r1 = (const uint2*)(zb + ((size_t)j1 << 7));
            const uint2* r2 = (const uint2*)(zb + ((size_t)j2 << 7));
            uint2 u1 = __ldg(&r1[lane]);
            uint2 u2 = __ldg(&r2[lane]);
            m01 = __hmax2(m01, *reinterpret_cast<__half2*>(&u1.x));
            m23 = __hmax2(m23, *reinterpret_cast<__half2*>(&u1.y));
            m01 = __hmax2(m01, *reinterpret_cast<__half2*>(&u2.x));
            m23 = __hmax2(m23, *reinterpret_cast<__half2*>(&u2.y));
        }

        float2 f01 = __half22float2(m01);
        float2 f23 = __half22float2(m23);
        sout[4 * lane + 0][ql] = f01.x;
        sout[4 * lane + 1][ql] = f01.y;
        sout[4 * lane + 2][ql] = f23.x;
        sout[4 * lane + 3][ql] = f23.y;
    }
    __syncthreads();

    float* ob = out + (size_t)b * C * N + n0;
    for (int i = tid; i < 128 * 32; i += 256) {
        int c = i >> 5, nn = i & 31;
        ob[(size_t)c * N + nn] = sout[c][nn];
    }
}

// ---------------------------------------------------------------------------
extern "C" void kernel_launch(void* const* d_in, const int* in_sizes, int n_in,
                              void* d_out, int out_size)
{
    const float* xyz   = (const float*)d_in[0];
    const float* x     = (const float*)d_in[1];
    const float* W     = (const float*)d_in[2];
    const float* gamma = (const float*)d_in[3];
    const float* beta  = (const float*)d_in[4];
    const float* rmean = (const float*)d_in[5];
    const float* rvar  = (const float*)d_in[6];
    float* out = (float*)d_out;

    static constexpr int FUSED_SMEM = 16 * 256 * 8 + 1024 * 16 + 64 * 5 * 4; // 50048B
    cudaFuncSetAttribute(fused_kernel,
                         cudaFuncAttributeMaxDynamicSharedMemorySize, FUSED_SMEM);

    // launch order keeps the fused kernel at flat launch index 3 (ncu slot)
    qsort_kernel<<<B, 512>>>(xyz);
    dummy_kernel<<<1, 1>>>();
    dummy_kernel<<<1, 1>>>();
    fused_kernel<<<1536, 256, FUSED_SMEM>>>(x, W, gamma, beta, rmean, rvar);
    gather_kernel<<<dim3(N / 32, B), 256>>>(out);
}

// round 15
// speedup vs baseline: 1.5071x; 1.5071x over previous
#include <cuda_runtime.h>
#include <cuda_bf16.h>
#include <cuda_fp16.h>
#include <math_constants.h>

#define FULL 0xffffffffu

static constexpr int B = 8;
static constexpr int N = 4096;
static constexpr int C = 128;
static constexpr int KNN = 16;

typedef unsigned long long ull;

// scratch (device globals: no allocation allowed)
__device__ __half g_zbn[B * N * C];    // zbn[b][n][c] fp16, n-major rows 256B
__device__ float4 g_srt[B * N];        // points in Morton-rank order (x,y,z,|p|^2)
__device__ int    g_sidx[B * N];       // Morton rank -> original index
__device__ int    g_idx[B * N * KNN];  // 16 NN orig indices per query

// ---------------------------------------------------------------------------
// dummy kernel (launch-slot shim so ncu's flat launch #3 is the fused kernel)
// ---------------------------------------------------------------------------
__global__ void dummy_kernel() {}

// ---------------------------------------------------------------------------
// Kernel 0: per-batch Morton counting sort (loads xyz, computes norms inline,
// scatters points + orig indices in Morton-rank order). 512 thr/block, 1/batch.
// ---------------------------------------------------------------------------
__device__ __forceinline__ int part4(int v) {
    return (v & 1) | ((v & 2) << 2) | ((v & 4) << 4) | ((v & 8) << 6);
}

__global__ __launch_bounds__(512) void qsort_kernel(const float* __restrict__ xyz)
{
    __shared__ int hist[4096];
    __shared__ int tsum[512];

    const int b   = blockIdx.x;
    const int tid = threadIdx.x;

    for (int i = tid; i < 4096; i += 512) hist[i] = 0;
    __syncthreads();

    float4 p[8];
    int cell[8];
#pragma unroll
    for (int k = 0; k < 8; ++k) {
        int i = tid + k * 512;
        const float* src = xyz + ((size_t)b * N + i) * 3;
        float px = src[0], py = src[1], pz = src[2];
        p[k] = make_float4(px, py, pz, px * px + py * py + pz * pz);
        int ix = min(15, max(0, (int)(px * 2.5f + 8.0f)));
        int iy = min(15, max(0, (int)(py * 2.5f + 8.0f)));
        int iz = min(15, max(0, (int)(pz * 2.5f + 8.0f)));
        int m = (part4(ix) << 2) | (part4(iy) << 1) | part4(iz);
        cell[k] = m;
        atomicAdd(&hist[m], 1);
    }
    __syncthreads();

    // exclusive prefix sum over 4096 bins (8 per thread + Hillis-Steele)
    const int base = tid * 8;
    int s = 0;
#pragma unroll
    for (int j = 0; j < 8; ++j) s += hist[base + j];
    tsum[tid] = s;
    __syncthreads();
    for (int off = 1; off < 512; off <<= 1) {
        int v = (tid >= off) ? tsum[tid - off] : 0;
        __syncthreads();
        tsum[tid] += v;
        __syncthreads();
    }
    int run = (tid ? tsum[tid - 1] : 0);
#pragma unroll
    for (int j = 0; j < 8; ++j) { int h = hist[base + j]; hist[base + j] = run; run += h; }
    __syncthreads();

    // scatter: rank = atomic cursor within cell
#pragma unroll
    for (int k = 0; k < 8; ++k) {
        int i = tid + k * 512;
        int r = atomicAdd(&hist[cell[k]], 1);
        g_srt[(size_t)b * N + r]  = p[k];
        g_sidx[(size_t)b * N + r] = i;
    }
}

// ---------------------------------------------------------------------------
// Role A: GEMM + BN + ReLU -> fp16 zbn. 64n x 64c tile, 16 acc/thread.
// ---------------------------------------------------------------------------
__device__ __forceinline__ void gemm_role(
    char* smem_raw, int gb,
    const float* __restrict__ x, const float* __restrict__ W,
    const float* __restrict__ gamma, const float* __restrict__ beta,
    const float* __restrict__ rmean, const float* __restrict__ rvar)
{
    float (*xs)[64] = (float(*)[64])smem_raw;                  // [32][64]
    float (*ws)[64] = (float(*)[64])(smem_raw + 32 * 64 * 4);  // [32][64] swizzled

    const int b      = gb >> 7;          // /128
    const int rem    = gb & 127;
    const int chalf  = rem >> 6;         // c-half 0/1
    const int n0     = (rem & 63) * 64;
    const int c0base = chalf * 64;

    const int tid = threadIdx.x;
    const int tc  = tid & 15;            // 16 c-groups x 4c
    const int tn  = tid >> 4;            // 16 n-groups x 4n

    float acc[4][4];
#pragma unroll
    for (int j = 0; j < 4; ++j)
#pragma unroll
        for (int i = 0; i < 4; ++i) acc[j][i] = 0.0f;

    const float* xb = x + (size_t)b * C * N;

    for (int k0 = 0; k0 < C; k0 += 32) {
#pragma unroll
        for (int i = tid; i < 32 * 64; i += 256) {
            int kk = i >> 6, nn = i & 63;
            xs[kk][nn] = xb[(size_t)(k0 + kk) * N + n0 + nn];
        }
#pragma unroll
        for (int i = tid; i < 32 * 64; i += 256) {
            int c = i >> 5, kk = i & 31;   // c' 0..63
            ws[kk][c ^ ((kk & 15) << 2)] = W[(c0base + c) * C + k0 + kk];
        }
        __syncthreads();

#pragma unroll
        for (int kk = 0; kk < 32; ++kk) {
            float4 wv = *(const float4*)&ws[kk][((tc ^ (kk & 15)) << 2)];
            float4 xv = *(const float4*)&xs[kk][tn * 4];
            float wj[4] = {wv.x, wv.y, wv.z, wv.w};
            float xi[4] = {xv.x, xv.y, xv.z, xv.w};
#pragma unroll
            for (int j = 0; j < 4; ++j)
#pragma unroll
                for (int i = 0; i < 4; ++i)
                    acc[j][i] = fmaf(wj[j], xi[i], acc[j][i]);
        }
        __syncthreads();
    }

    const int c0 = c0base + tc * 4;
    float sc[4], bi[4];
#pragma unroll
    for (int j = 0; j < 4; ++j) {
        sc[j] = gamma[c0 + j] * rsqrtf(rvar[c0 + j] + 1e-5f);
        bi[j] = beta[c0 + j] - rmean[c0 + j] * sc[j];
    }
#pragma unroll
    for (int i = 0; i < 4; ++i) {
        int n = n0 + tn * 4 + i;
        float ox = fmaxf(fmaf(acc[0][i], sc[0], bi[0]), 0.0f);
        float oy = fmaxf(fmaf(acc[1][i], sc[1], bi[1]), 0.0f);
        float oz = fmaxf(fmaf(acc[2][i], sc[2], bi[2]), 0.0f);
        float ow = fmaxf(fmaf(acc[3][i], sc[3], bi[3]), 0.0f);
        __half2 h01 = __floats2half2_rn(ox, oy);
        __half2 h23 = __floats2half2_rn(oz, ow);
        uint2 u;
        u.x = *reinterpret_cast<unsigned*>(&h01);
        u.y = *reinterpret_cast<unsigned*>(&h23);
        *(uint2*)&g_zbn[((size_t)b * N + n) * C + c0] = u;
    }
}

// ---------------------------------------------------------------------------
// Role B: top-16 KNN over Morton-rank space (R13 scan order: splits ascending,
// chunks ascending). NEW: value-only seed over the warp's own 32-query window
// gives a near-final initial threshold WITHOUT recording indices; main scan
// then covers all 1024 own-split candidates with accept d <= fthr into an
// empty list. Every true top-16 member has d <= fthr -> exact; arrival order
// ascending-index with strict-incumbent insert -> same tie resolution as R13.
// ---------------------------------------------------------------------------
__device__ __forceinline__ void insert16(float (&tv)[16], int (&ti)[16],
                                         float e, int jj)
{
#pragma unroll
    for (int t = 15; t >= 0; --t) {
        bool gt  = tv[t] > e;                   // strict: ties keep incumbent
        bool gtp = (t > 0) && (tv[t - 1] > e);
        float nv = gtp ? tv[t - 1] : e;
        int   ni = gtp ? ti[t - 1] : jj;
        if (gt) { tv[t] = nv; ti[t] = ni; }
    }
}

// value-only sorted insert (seed threshold): 3 ops/slot
__device__ __forceinline__ void vinsert16(float (&tv)[16], float e)
{
#pragma unroll
    for (int t = 15; t >= 0; --t) {
        bool gtp = (t > 0) && (tv[t - 1] > e);
        float nv = gtp ? tv[t - 1] : e;
        if (tv[t] > e) tv[t] = nv;
    }
}

__device__ __forceinline__ void knn_role(char* smem_raw, int kb)
{
    ull    (*buf)[256] = (ull(*)[256])smem_raw;                  // [16][256] 32KB
    float4* tile = (float4*)(smem_raw + 16 * 256 * 8);           // [1024] 16KB
    float  (*sthr)[5] = (float(*)[5])(smem_raw + 16 * 256 * 8 + 1024 * 16);

    const int tid  = threadIdx.x;
    const int u    = tid & 63;                   // query slot in block
    const int s    = tid >> 6;                   // split 0..3 (warp-homogeneous)
    const int b    = kb >> 6;                    // batch
    const int w    = kb & 63;                    // query-window id
    const int qrk  = w * 64 + u;                 // my query's Morton rank
    const int wbase = w * 64 + ((u >> 5) << 5);  // warp's 32-query window base

    // init shared thresholds
    for (int i = tid; i < 64 * 5; i += 256) ((float*)sthr)[i] = CUDART_INF_F;

    const float4* __restrict__ xb = g_srt + (size_t)b * N;
    const float4 Q = __ldg(&xb[qrk]);
    const float qs = Q.w;

    // ---- value-only seed: warp's own 32-window -> tight initial threshold.
    //      Warp-uniform broadcast loads; no indices recorded.
    float sv[16];
#pragma unroll
    for (int t = 0; t < 16; ++t) sv[t] = CUDART_INF_F;
#pragma unroll 1
    for (int jj = 0; jj < 32; ++jj) {
        float4 p = __ldg(&xb[wbase + jj]);
        float dot = Q.x * p.x;
        dot = fmaf(Q.y, p.y, dot);
        dot = fmaf(Q.z, p.z, dot);
        float d = fmaf(-2.0f, dot, qs + p.w);
        vinsert16(sv, d);
    }
    const float seedthr = sv[15];
    float fthr = seedthr;

    float tv[16]; int ti[16];
#pragma unroll
    for (int t = 0; t < 16; ++t) { tv[t] = CUDART_INF_F; ti[t] = 0; }

    const int lo = s << 10;                      // s * 1024
    const float4* __restrict__ mychunk = tile + (s << 8);

    unsigned addr0 = (unsigned)__cvta_generic_to_shared(&buf[0][0]) + tid * 8u;
    unsigned addr  = addr0;
    const unsigned athr = addr0 + 8u * 2048u;    // trigger: cnt >= 8 (stride 2048)

#define KNN_FLUSH() do {                                                      \
        int cnt = (int)((addr - addr0) >> 11);                                \
        int mx  = __reduce_max_sync(FULL, cnt);                               \
        for (int t = 0; t < mx; ++t) {                                        \
            ull e = buf[t][tid];                                              \
            float ed = (t < cnt) ? __uint_as_float((unsigned)(e >> 32))       \
                                 : CUDART_INF_F;                              \
            int   ej = (int)(unsigned)e;                                      \
            insert16(tv, ti, ed, ej);                                         \
        }                                                                     \
        addr = addr0;                                                         \
        sthr[u][s] = tv[15];                                                  \
        fthr = fminf(seedthr,                                                 \
               fminf(fminf(sthr[u][0], sthr[u][1]),                           \
                     fminf(sthr[u][2], sthr[u][3])));                         \
    } while (0)

#pragma unroll 1
    for (int it = 0; it < 4; ++it) {
        // ---- stage 4x256 chunk tile (coalesced; barrier protects reads) ----
        __syncthreads();
#pragma unroll
        for (int k = 0; k < 4; ++k) {
            int flat = tid + (k << 8);           // 0..1023
            int ch = flat >> 8, off = flat & 255;
            tile[flat] = __ldg(&xb[(ch << 10) + (it << 8) + off]);
        }
        __syncthreads();

        const int jbase = lo + (it << 8);

        // ---- scan chunk: two 4-candidate phases (A: distances, B: accepts),
        //      flush check per 8 candidates; accept d <= fthr ----
#pragma unroll 1
        for (int t0 = 0; t0 < 256; t0 += 8) {
#pragma unroll
            for (int h = 0; h < 2; ++h) {
                float d[4];
#pragma unroll
                for (int uu = 0; uu < 4; ++uu) {
                    float4 p = mychunk[t0 + 4 * h + uu];
                    float dot = Q.x * p.x;
                    dot = fmaf(Q.y, p.y, dot);
                    dot = fmaf(Q.z, p.z, dot);
                    d[uu] = fmaf(-2.0f, dot, qs + p.w);
                }
#pragma unroll
                for (int uu = 0; uu < 4; ++uu) {
                    int j = jbase + t0 + 4 * h + uu;
                    unsigned db = __float_as_uint(d[uu]);
                    asm volatile(
                        "{\n\t"
                        ".reg .pred p;\n\t"
                        "setp.le.f32 p, %1, %2;\n\t"
                        "@p st.shared.v2.b32 [%0], {%3, %4};\n\t"
                        "@p add.u32 %0, %0, 2048;\n\t"
                        "}"
                        : "+r"(addr) : "f"(d[uu]), "f"(fthr), "r"(j), "r"(db) : "memory");
                }
            }
            if (__any_sync(FULL, addr >= athr)) KNN_FLUSH();
        }
    }
    // ---- final flush ----
    if (__any_sync(FULL, addr != addr0)) KNN_FLUSH();
#undef KNN_FLUSH

    // ---- merge splits 1..3 into split 0; splits scan disjoint rank ranges
    //      so no dedup needed. INF slots never insert. Staging overlays buf. ----
    __syncthreads();                             // all flush reads of buf done
    float (*mD)[3][17] = (float(*)[3][17])&buf[0][0];
    int   (*mI)[3][17] = (int(*)[3][17])((float*)&buf[0][0] + 64 * 3 * 17);

    if (s != 0) {
#pragma unroll
        for (int t = 0; t < 16; ++t) {
            mD[u][s - 1][t] = tv[t];
            mI[u][s - 1][t] = ti[t];
        }
    }
    __syncthreads();
    if (s == 0) {
#pragma unroll 1
        for (int k = 0; k < 3; ++k)
#pragma unroll 1
            for (int t = 0; t < 16; ++t)
                insert16(tv, ti, mD[u][k][t], mI[u][k][t]);

        // map ranks -> original indices; write to the query's original slot
        const int* __restrict__ sidx = g_sidx + (size_t)b * N;
        int orig = __ldg(&sidx[qrk]);
        int* op = g_idx + ((size_t)b * N + orig) * KNN;
#pragma unroll
        for (int t = 0; t < 16; ++t) op[t] = __ldg(&sidx[ti[t]]);
    }
}

// ---------------------------------------------------------------------------
// Fused kernel: blocks [0,512) = KNN (long pole, scheduled first);
// blocks [512,1536) = GEMM (backfills, FFMA fills KNN's ALU-stall slots).
// __launch_bounds__(256,4): 64-reg ceiling -> 4 blocks/SM with 50KB smem.
// ---------------------------------------------------------------------------
extern __shared__ char smem_raw[];

__global__ __launch_bounds__(256, 4) void fused_kernel(
    const float* __restrict__ x, const float* __restrict__ W,
    const float* __restrict__ gamma, const float* __restrict__ beta,
    const float* __restrict__ rmean, const float* __restrict__ rvar)
{
    int bx = blockIdx.x;
    if (bx < 512)
        knn_role(smem_raw, bx);
    else
        gemm_role(smem_raw, bx - 512, x, W, gamma, beta, rmean, rvar);
}

// ---------------------------------------------------------------------------
// Kernel 3: gather-max over 16 neighbors (fp16 rows) + transpose to [B][C][N].
// ---------------------------------------------------------------------------
__global__ __launch_bounds__(256) void gather_kernel(float* __restrict__ out)
{
    __shared__ float sout[128][33];

    const int b    = blockIdx.y;
    const int n0   = blockIdx.x * 32;
    const int tid  = threadIdx.x;
    const int w    = tid >> 5;
    const int lane = tid & 31;

    const __half* __restrict__ zb = g_zbn + (size_t)b * N * C;

    for (int s = 0; s < 4; ++s) {
        const int ql = w * 4 + s;
        const int n  = n0 + ql;
        int myidx = (lane < 16) ? g_idx[((size_t)b * N + n) * KNN + lane] : 0;

        __half2 m01 = __float2half2_rn(0.0f);   // post-ReLU >= 0
        __half2 m23 = __float2half2_rn(0.0f);
#pragma unroll
        for (int t = 0; t < KNN; t += 2) {
            int j1 = __shfl_sync(FULL, myidx, t);
            int j2 = __shfl_sync(FULL, myidx, t + 1);
            const uint2* r1 = (const uint2*)(zb + ((size_t)j1 << 7));
            const uint2* r2 = (const uint2*)(zb + ((size_t)j2 << 7));
            uint2 u1 = __ldg(&r1[lane]);
            uint2 u2 = __ldg(&r2[lane]);
            m01 = __hmax2(m01, *reinterpret_cast<__half2*>(&u1.x));
            m23 = __hmax2(m23, *reinterpret_cast<__half2*>(&u1.y));
            m01 = __hmax2(m01, *reinterpret_cast<__half2*>(&u2.x));
            m23 = __hmax2(m23, *reinterpret_cast<__half2*>(&u2.y));
        }

        float2 f01 = __half22float2(m01);
        float2 f23 = __half22float2(m23);
        sout[4 * lane + 0][ql] = f01.x;
        sout[4 * lane + 1][ql] = f01.y;
        sout[4 * lane + 2][ql] = f23.x;
        sout[4 * lane + 3][ql] = f23.y;
    }
    __syncthreads();

    float* ob = out + (size_t)b * C * N + n0;
    for (int i = tid; i < 128 * 32; i += 256) {
        int c = i >> 5, nn = i & 31;
        ob[(size_t)c * N + nn] = sout[c][nn];
    }
}

// ---------------------------------------------------------------------------
extern "C" void kernel_launch(void* const* d_in, const int* in_sizes, int n_in,
                              void* d_out, int out_size)
{
    const float* xyz   = (const float*)d_in[0];
    const float* x     = (const float*)d_in[1];
    const float* W     = (const float*)d_in[2];
    const float* gamma = (const float*)d_in[3];
    const float* beta  = (const float*)d_in[4];
    const float* rmean = (const float*)d_in[5];
    const float* rvar  = (const float*)d_in[6];
    float* out = (float*)d_out;

    static constexpr int FUSED_SMEM = 16 * 256 * 8 + 1024 * 16 + 64 * 5 * 4; // 50048B
    cudaFuncSetAttribute(fused_kernel,
                         cudaFuncAttributeMaxDynamicSharedMemorySize, FUSED_SMEM);

    // launch order keeps the fused kernel at flat launch index 3 (ncu slot)
    qsort_kernel<<<B, 512>>>(xyz);
    dummy_kernel<<<1, 1>>>();
    dummy_kernel<<<1, 1>>>();
    fused_kernel<<<1536, 256, FUSED_SMEM>>>(x, W, gamma, beta, rmean, rvar);
    gather_kernel<<<dim3(N / 32, B), 256>>>(out);
}

// round 16
// speedup vs baseline: 1.8611x; 1.2349x over previous
#include <cuda_runtime.h>
#include <cuda_bf16.h>
#include <cuda_fp16.h>
#include <math_constants.h>

#define FULL 0xffffffffu

static constexpr int B = 8;
static constexpr int N = 4096;
static constexpr int C = 128;
static constexpr int KNN = 16;

typedef unsigned long long ull;

// scratch (device globals: no allocation allowed)
__device__ __half g_zbn[B * N * C];    // zbn[b][n][c] fp16, n-major rows 256B
__device__ float4 g_xyz4[B * N];       // (x,y,z,|p|^2) original order
__device__ int    g_idx[B * N * KNN];  // 16 NN indices per query
__device__ int    g_qord[B * N];       // Morton-rank -> original query index

// ---------------------------------------------------------------------------
// Kernel 0: fused prep + Morton counting sort. Loads xyz once, writes
// g_xyz4 (original order, with |p|^2) and g_qord (queries sorted by 12-bit
// Morton cell so warp lanes are spatially adjacent). One 512-thr block/batch.
// Order within a cell is nondeterministic but per-query KNN output is
// order-independent -> deterministic results.
// ---------------------------------------------------------------------------
__device__ __forceinline__ int part4(int v) {
    return (v & 1) | ((v & 2) << 2) | ((v & 4) << 4) | ((v & 8) << 6);
}

__global__ __launch_bounds__(512) void qsort_kernel(const float* __restrict__ xyz)
{
    __shared__ int hist[4096];
    __shared__ int tsum[512];

    const int b   = blockIdx.x;
    const int tid = threadIdx.x;

    for (int i = tid; i < 4096; i += 512) hist[i] = 0;
    __syncthreads();

    int cell[8];
#pragma unroll
    for (int k = 0; k < 8; ++k) {
        int i = tid + k * 512;
        const float* src = xyz + ((size_t)b * N + i) * 3;
        float px = src[0], py = src[1], pz = src[2];
        g_xyz4[(size_t)b * N + i] =
            make_float4(px, py, pz, px * px + py * py + pz * pz);
        int ix = min(15, max(0, (int)(px * 2.5f + 8.0f)));
        int iy = min(15, max(0, (int)(py * 2.5f + 8.0f)));
        int iz = min(15, max(0, (int)(pz * 2.5f + 8.0f)));
        int m = (part4(ix) << 2) | (part4(iy) << 1) | part4(iz);
        cell[k] = m;
        atomicAdd(&hist[m], 1);
    }
    __syncthreads();

    // exclusive prefix sum over 4096 bins (8 per thread + Hillis-Steele)
    const int base = tid * 8;
    int s = 0;
#pragma unroll
    for (int j = 0; j < 8; ++j) s += hist[base + j];
    tsum[tid] = s;
    __syncthreads();
    for (int off = 1; off < 512; off <<= 1) {
        int v = (tid >= off) ? tsum[tid - off] : 0;
        __syncthreads();
        tsum[tid] += v;
        __syncthreads();
    }
    int run = (tid ? tsum[tid - 1] : 0);
#pragma unroll
    for (int j = 0; j < 8; ++j) { int h = hist[base + j]; hist[base + j] = run; run += h; }
    __syncthreads();

    // scatter: rank = atomic cursor within cell
#pragma unroll
    for (int k = 0; k < 8; ++k) {
        int i = tid + k * 512;
        int r = atomicAdd(&hist[cell[k]], 1);
        g_qord[(size_t)b * N + r] = i;
    }
}

// ---------------------------------------------------------------------------
// Role A: GEMM + BN + ReLU -> fp16 zbn. 64n x 64c tile, 16 acc/thread.
// ---------------------------------------------------------------------------
__device__ __forceinline__ void gemm_role(
    char* smem_raw, int gb,
    const float* __restrict__ x, const float* __restrict__ W,
    const float* __restrict__ gamma, const float* __restrict__ beta,
    const float* __restrict__ rmean, const float* __restrict__ rvar)
{
    float (*xs)[64] = (float(*)[64])smem_raw;                  // [32][64]
    float (*ws)[64] = (float(*)[64])(smem_raw + 32 * 64 * 4);  // [32][64] swizzled

    const int b      = gb >> 7;          // /128
    const int rem    = gb & 127;
    const int chalf  = rem >> 6;         // c-half 0/1
    const int n0     = (rem & 63) * 64;
    const int c0base = chalf * 64;

    const int tid = threadIdx.x;
    const int tc  = tid & 15;            // 16 c-groups x 4c
    const int tn  = tid >> 4;            // 16 n-groups x 4n

    float acc[4][4];
#pragma unroll
    for (int j = 0; j < 4; ++j)
#pragma unroll
        for (int i = 0; i < 4; ++i) acc[j][i] = 0.0f;

    const float* xb = x + (size_t)b * C * N;

    for (int k0 = 0; k0 < C; k0 += 32) {
#pragma unroll
        for (int i = tid; i < 32 * 64; i += 256) {
            int kk = i >> 6, nn = i & 63;
            xs[kk][nn] = xb[(size_t)(k0 + kk) * N + n0 + nn];
        }
#pragma unroll
        for (int i = tid; i < 32 * 64; i += 256) {
            int c = i >> 5, kk = i & 31;   // c' 0..63
            ws[kk][c ^ ((kk & 15) << 2)] = W[(c0base + c) * C + k0 + kk];
        }
        __syncthreads();

#pragma unroll
        for (int kk = 0; kk < 32; ++kk) {
            float4 wv = *(const float4*)&ws[kk][((tc ^ (kk & 15)) << 2)];
            float4 xv = *(const float4*)&xs[kk][tn * 4];
            float wj[4] = {wv.x, wv.y, wv.z, wv.w};
            float xi[4] = {xv.x, xv.y, xv.z, xv.w};
#pragma unroll
            for (int j = 0; j < 4; ++j)
#pragma unroll
                for (int i = 0; i < 4; ++i)
                    acc[j][i] = fmaf(wj[j], xi[i], acc[j][i]);
        }
        __syncthreads();
    }

    const int c0 = c0base + tc * 4;
    float sc[4], bi[4];
#pragma unroll
    for (int j = 0; j < 4; ++j) {
        sc[j] = gamma[c0 + j] * rsqrtf(rvar[c0 + j] + 1e-5f);
        bi[j] = beta[c0 + j] - rmean[c0 + j] * sc[j];
    }
#pragma unroll
    for (int i = 0; i < 4; ++i) {
        int n = n0 + tn * 4 + i;
        float ox = fmaxf(fmaf(acc[0][i], sc[0], bi[0]), 0.0f);
        float oy = fmaxf(fmaf(acc[1][i], sc[1], bi[1]), 0.0f);
        float oz = fmaxf(fmaf(acc[2][i], sc[2], bi[2]), 0.0f);
        float ow = fmaxf(fmaf(acc[3][i], sc[3], bi[3]), 0.0f);
        __half2 h01 = __floats2half2_rn(ox, oy);
        __half2 h23 = __floats2half2_rn(oz, ow);
        uint2 u;
        u.x = *reinterpret_cast<unsigned*>(&h01);
        u.y = *reinterpret_cast<unsigned*>(&h23);
        *(uint2*)&g_zbn[((size_t)b * N + n) * C + c0] = u;
    }
}

// ---------------------------------------------------------------------------
// Role B: top-16 KNN (round-13 body verbatim). Queries taken in Morton-rank
// order (warp lanes spatially adjacent -> correlated accepts); candidates
// scanned in ORIGINAL index order (splits ascending, chunks ascending).
// Shared cross-split threshold; branch-free accepts; deferred flush.
// ---------------------------------------------------------------------------
__device__ __forceinline__ void insert16(float (&tv)[16], int (&ti)[16],
                                         float e, int jj)
{
#pragma unroll
    for (int t = 15; t >= 0; --t) {
        bool gt  = tv[t] > e;                   // strict: ties keep incumbent
        bool gtp = (t > 0) && (tv[t - 1] > e);
        float nv = gtp ? tv[t - 1] : e;
        int   ni = gtp ? ti[t - 1] : jj;
        if (gt) { tv[t] = nv; ti[t] = ni; }
    }
}

__device__ __forceinline__ void knn_role(char* smem_raw, int kb)
{
    ull    (*buf)[256] = (ull(*)[256])smem_raw;                  // [16][256] 32KB
    float4* tile = (float4*)(smem_raw + 16 * 256 * 8);           // [1024] 16KB
    float  (*sthr)[5] = (float(*)[5])(smem_raw + 16 * 256 * 8 + 1024 * 16);

    const int tid  = threadIdx.x;
    const int u    = tid & 63;                   // query slot in block
    const int s    = tid >> 6;                   // split 0..3 (warp-homogeneous)
    const int b    = kb >> 6;                    // batch
    const int qrk  = (kb & 63) * 64 + u;         // Morton rank
    const int q    = g_qord[(size_t)b * N + qrk];

    // init shared thresholds
    for (int i = tid; i < 64 * 5; i += 256) ((float*)sthr)[i] = CUDART_INF_F;

    const float4* __restrict__ xb = g_xyz4 + (size_t)b * N;
    const float4 Q = __ldg(&xb[q]);
    const float qs = Q.w;

    float tv[16]; int ti[16];
#pragma unroll
    for (int t = 0; t < 16; ++t) { tv[t] = CUDART_INF_F; ti[t] = 0; }

    const int lo = s << 10;                      // s * 1024
    const float4* __restrict__ mychunk = tile + (s << 8);

    unsigned addr0 = (unsigned)__cvta_generic_to_shared(&buf[0][0]) + tid * 8u;
    unsigned addr  = addr0;
    const unsigned athr = addr0 + 8u * 2048u;    // trigger: cnt >= 8 (stride 2048)
    float fthr = CUDART_INF_F;

#define KNN_FLUSH() do {                                                      \
        int cnt = (int)((addr - addr0) >> 11);                                \
        int mx  = __reduce_max_sync(FULL, cnt);                               \
        for (int t = 0; t < mx; ++t) {                                        \
            ull e = buf[t][tid];                                              \
            float ed = (t < cnt) ? __uint_as_float((unsigned)(e >> 32))       \
                                 : CUDART_INF_F;                              \
            int   ej = (int)(unsigned)e;                                      \
            insert16(tv, ti, ed, ej);                                         \
        }                                                                     \
        addr = addr0;                                                         \
        sthr[u][s] = tv[15];                                                  \
        fthr = fminf(fminf(sthr[u][0], sthr[u][1]),                           \
                     fminf(sthr[u][2], sthr[u][3]));                          \
    } while (0)

#pragma unroll 1
    for (int it = 0; it < 4; ++it) {
        // ---- stage 4x256 chunk tile (coalesced; barrier protects reads) ----
        __syncthreads();
#pragma unroll
        for (int k = 0; k < 4; ++k) {
            int flat = tid + (k << 8);           // 0..1023
            int ch = flat >> 8, off = flat & 255;
            tile[flat] = __ldg(&xb[(ch << 10) + (it << 8) + off]);
        }
        __syncthreads();

        const int jbase = lo + (it << 8);
        int t0 = 0;

        if (it == 0) {
            // ---- seed: first 16 candidates of own range, co-executed inserts ----
#pragma unroll 1
            for (int jj = 0; jj < 16; ++jj) {
                float4 p = mychunk[jj];
                float dot = Q.x * p.x;
                dot = fmaf(Q.y, p.y, dot);
                dot = fmaf(Q.z, p.z, dot);
                float d = fmaf(-2.0f, dot, qs + p.w);
                insert16(tv, ti, d, jbase + jj);
            }
            sthr[u][s] = tv[15];
            fthr = fminf(fminf(sthr[u][0], sthr[u][1]),
                         fminf(sthr[u][2], sthr[u][3]));
            t0 = 16;
        }

        // ---- scan chunk: two 4-candidate phases (A: distances, B: accepts),
        //      flush check per 8 candidates ----
#pragma unroll 1
        for (; t0 < 256; t0 += 8) {
#pragma unroll
            for (int h = 0; h < 2; ++h) {
                float d[4];
#pragma unroll
                for (int uu = 0; uu < 4; ++uu) {
                    float4 p = mychunk[t0 + 4 * h + uu];
                    float dot = Q.x * p.x;
                    dot = fmaf(Q.y, p.y, dot);
                    dot = fmaf(Q.z, p.z, dot);
                    d[uu] = fmaf(-2.0f, dot, qs + p.w);
                }
#pragma unroll
                for (int uu = 0; uu < 4; ++uu) {
                    int j = jbase + t0 + 4 * h + uu;
                    unsigned db = __float_as_uint(d[uu]);
                    asm volatile(
                        "{\n\t"
                        ".reg .pred p;\n\t"
                        "setp.lt.f32 p, %1, %2;\n\t"
                        "@p st.shared.v2.b32 [%0], {%3, %4};\n\t"
                        "@p add.u32 %0, %0, 2048;\n\t"
                        "}"
                        : "+r"(addr) : "f"(d[uu]), "f"(fthr), "r"(j), "r"(db) : "memory");
                }
            }
            if (__any_sync(FULL, addr >= athr)) KNN_FLUSH();
        }
    }
    // ---- final flush ----
    if (__any_sync(FULL, addr != addr0)) KNN_FLUSH();
#undef KNN_FLUSH

    // ---- merge splits 1..3 into split 0 (ascending split order preserves
    //      lower-index-on-tie). Staging overlays the dead accept buffer. ----
    __syncthreads();                             // all flush reads of buf done
    float (*mD)[3][17] = (float(*)[3][17])&buf[0][0];
    int   (*mI)[3][17] = (int(*)[3][17])((float*)&buf[0][0] + 64 * 3 * 17);

    if (s != 0) {
#pragma unroll
        for (int t = 0; t < 16; ++t) {
            mD[u][s - 1][t] = tv[t];
            mI[u][s - 1][t] = ti[t];
        }
    }
    __syncthreads();
    if (s == 0) {
#pragma unroll 1
        for (int k = 0; k < 3; ++k)
#pragma unroll 1
            for (int t = 0; t < 16; ++t)
                insert16(tv, ti, mD[u][k][t], mI[u][k][t]);

        int* op = g_idx + ((size_t)b * N + q) * KNN;
#pragma unroll
        for (int t = 0; t < 16; ++t) op[t] = ti[t];
    }
}

// ---------------------------------------------------------------------------
// Fused kernel: blocks [0,512) = KNN (long pole, scheduled first);
// blocks [512,1536) = GEMM (backfills, FFMA fills KNN's ALU-stall slots).
// __launch_bounds__(256,4): 64-reg ceiling -> 4 blocks/SM with 50KB smem.
// ---------------------------------------------------------------------------
extern __shared__ char smem_raw[];

__global__ __launch_bounds__(256, 4) void fused_kernel(
    const float* __restrict__ x, const float* __restrict__ W,
    const float* __restrict__ gamma, const float* __restrict__ beta,
    const float* __restrict__ rmean, const float* __restrict__ rvar)
{
    int bx = blockIdx.x;
    if (bx < 512)
        knn_role(smem_raw, bx);
    else
        gemm_role(smem_raw, bx - 512, x, W, gamma, beta, rmean, rvar);
}

// ---------------------------------------------------------------------------
// Kernel 3: gather-max over 16 neighbors (fp16 rows) + transpose to [B][C][N].
// ---------------------------------------------------------------------------
__global__ __launch_bounds__(256) void gather_kernel(float* __restrict__ out)
{
    __shared__ float sout[128][33];

    const int b    = blockIdx.y;
    const int n0   = blockIdx.x * 32;
    const int tid  = threadIdx.x;
    const int w    = tid >> 5;
    const int lane = tid & 31;

    const __half* __restrict__ zb = g_zbn + (size_t)b * N * C;

    for (int s = 0; s < 4; ++s) {
        const int ql = w * 4 + s;
        const int n  = n0 + ql;
        int myidx = (lane < 16) ? g_idx[((size_t)b * N + n) * KNN + lane] : 0;

        __half2 m01 = __float2half2_rn(0.0f);   // post-ReLU >= 0
        __half2 m23 = __float2half2_rn(0.0f);
#pragma unroll
        for (int t = 0; t < KNN; t += 2) {
            int j1 = __shfl_sync(FULL, myidx, t);
            int j2 = __shfl_sync(FULL, myidx, t + 1);
            const uint2* r1 = (const uint2*)(zb + ((size_t)j1 << 7));
            const uint2* r2 = (const uint2*)(zb + ((size_t)j2 << 7));
            uint2 u1 = __ldg(&r1[lane]);
            uint2 u2 = __ldg(&r2[lane]);
            m01 = __hmax2(m01, *reinterpret_cast<__half2*>(&u1.x));
            m23 = __hmax2(m23, *reinterpret_cast<__half2*>(&u1.y));
            m01 = __hmax2(m01, *reinterpret_cast<__half2*>(&u2.x));
            m23 = __hmax2(m23, *reinterpret_cast<__half2*>(&u2.y));
        }

        float2 f01 = __half22float2(m01);
        float2 f23 = __half22float2(m23);
        sout[4 * lane + 0][ql] = f01.x;
        sout[4 * lane + 1][ql] = f01.y;
        sout[4 * lane + 2][ql] = f23.x;
        sout[4 * lane + 3][ql] = f23.y;
    }
    __syncthreads();

    float* ob = out + (size_t)b * C * N + n0;
    for (int i = tid; i < 128 * 32; i += 256) {
        int c = i >> 5, nn = i & 31;
        ob[(size_t)c * N + nn] = sout[c][nn];
    }
}

// ---------------------------------------------------------------------------
extern "C" void kernel_launch(void* const* d_in, const int* in_sizes, int n_in,
                              void* d_out, int out_size)
{
    const float* xyz   = (const float*)d_in[0];
    const float* x     = (const float*)d_in[1];
    const float* W     = (const float*)d_in[2];
    const float* gamma = (const float*)d_in[3];
    const float* beta  = (const float*)d_in[4];
    const float* rmean = (const float*)d_in[5];
    const float* rvar  = (const float*)d_in[6];
    float* out = (float*)d_out;

    static constexpr int FUSED_SMEM = 16 * 256 * 8 + 1024 * 16 + 64 * 5 * 4; // 50048B
    cudaFuncSetAttribute(fused_kernel,
                         cudaFuncAttributeMaxDynamicSharedMemorySize, FUSED_SMEM);

    qsort_kernel<<<B, 512>>>(xyz);
    fused_kernel<<<1536, 256, FUSED_SMEM>>>(x, W, gamma, beta, rmean, rvar);
    gather_kernel<<<dim3(N / 32, B), 256>>>(out);
}